// round 4
// baseline (speedup 1.0000x reference)
#include <cuda_runtime.h>
#include <math.h>

// Problem constants (fixed by the reference)
#define B_FRAMES 256
#define N_COLS   576
#define MR_ROWS  144
#define Z_LIFT   24
#define N_IT     3
#define ROW_DEG  15
#define N_MSG    (MR_ROWS * ROW_DEG)   // 2160
#define NB_A     ((MR_ROWS / Z_LIFT) * (N_COLS / Z_LIFT) * N_IT)  // 6*24*3 = 432

// Scratch: column indices of the 15 ones per check row (built from H each launch)
__device__ int g_row_cols[N_MSG];

// ---------------------------------------------------------------------------
// Kernel 1: extract the sparse row structure of H via warp ballot compaction.
// One warp per check row; 18 coalesced 32-wide chunks of the 576-col row.
// ---------------------------------------------------------------------------
__global__ void nms_prep_rows(const int* __restrict__ H) {
    int warp = (blockIdx.x * blockDim.x + threadIdx.x) >> 5;
    int lane = threadIdx.x & 31;
    if (warp >= MR_ROWS) return;
    const int* row = H + warp * N_COLS;
    int cnt = 0;
    #pragma unroll
    for (int base = 0; base < N_COLS; base += 32) {
        int v = row[base + lane];
        unsigned ball = __ballot_sync(0xffffffffu, v != 0);
        int before = __popc(ball & ((1u << lane) - 1u));
        if (v != 0) g_row_cols[warp * ROW_DEG + cnt + before] = base + lane;
        cnt += __popc(ball);
    }
}

// ---------------------------------------------------------------------------
// Kernel 2: one CTA per frame. All decoder state lives in shared memory.
// ---------------------------------------------------------------------------
#define BT 256

__global__ __launch_bounds__(BT) void nms_decode(
    const float* __restrict__ r,
    const float* __restrict__ alpha,
    const float* __restrict__ beta,
    float* __restrict__ out)
{
    __shared__ float s_r[N_COLS];
    __shared__ float s_sumE[N_COLS];
    __shared__ float s_M[N_MSG];
    __shared__ float s_E[N_MSG];
    __shared__ int   s_rc[N_MSG];
    __shared__ float s_a[NB_A];
    __shared__ float s_b[NB_A];

    const int b   = blockIdx.x;
    const int tid = threadIdx.x;

    // Stage inputs
    for (int i = tid; i < N_COLS; i += BT) s_r[i] = r[b * N_COLS + i];
    for (int i = tid; i < N_MSG;  i += BT) s_rc[i] = g_row_cols[i];
    for (int i = tid; i < NB_A;   i += BT) { s_a[i] = alpha[i]; s_b[i] = beta[i]; }
    __syncthreads();

    // Initial v->c messages: M[m,k] = r[col(m,k)]
    for (int e = tid; e < N_MSG; e += BT) s_M[e] = s_r[s_rc[e]];
    __syncthreads();

    for (int it = 0; it < N_IT; ++it) {
        // Zero the column accumulator (races with nothing pre-sync)
        for (int i = tid; i < N_COLS; i += BT) s_sumE[i] = 0.0f;

        // Check-node phase: one thread per check row.
        if (tid < MR_ROWS) {
            const int m = tid, base = m * ROW_DEG;
            float mv[ROW_DEG];
            int   cols[ROW_DEG];
            float min1 = INFINITY, min2 = INFINITY;
            int   kmin = 0;
            float sp = 1.0f;
            #pragma unroll
            for (int k = 0; k < ROW_DEG; ++k) {
                float v = s_M[base + k];
                mv[k] = v;
                cols[k] = s_rc[base + k];
                float av = fabsf(v);
                if (av < min1) { min2 = min1; min1 = av; kmin = k; }
                else if (av < min2) { min2 = av; }
                sp *= (v > 0.0f) ? 1.0f : ((v < 0.0f) ? -1.0f : 0.0f);
            }
            const int abase = (m / Z_LIFT) * ((N_COLS / Z_LIFT) * N_IT) + it;
            #pragma unroll
            for (int k = 0; k < ROW_DEG; ++k) {
                int   bc = cols[k] / Z_LIFT;
                float a  = s_a[abase + bc * N_IT];
                float bt = s_b[abase + bc * N_IT];
                float v  = mv[k];
                float s  = (v > 0.0f) ? 1.0f : ((v < 0.0f) ? -1.0f : 0.0f);
                float eabs = (k == kmin) ? min2 : min1;
                float mag  = eabs - bt;
                mag = (mag > 0.0f) ? mag : 0.0f;
                s_E[base + k] = a * sp * s * mag;
            }
        }
        __syncthreads();

        // Column sums: sum_E[n] = sum over rows containing n
        for (int e = tid; e < N_MSG; e += BT)
            atomicAdd(&s_sumE[s_rc[e]], s_E[e]);
        __syncthreads();

        // Variable-node phase (dead on the last iteration — skip it)
        if (it < N_IT - 1) {
            for (int e = tid; e < N_MSG; e += BT) {
                int c = s_rc[e];
                s_M[e] = s_r[c] + s_sumE[c] - s_E[e];
            }
            __syncthreads();
        }
    }

    // Posterior LLRs
    for (int i = tid; i < N_COLS; i += BT)
        out[b * N_COLS + i] = s_r[i] + s_sumE[i];
}

extern "C" void kernel_launch(void* const* d_in, const int* in_sizes, int n_in,
                              void* d_out, int out_size) {
    const float* r     = (const float*)d_in[0];   // (256, 576)
    const float* alpha = (const float*)d_in[1];   // (6, 24, 3)
    const float* beta  = (const float*)d_in[2];   // (6, 24, 3)
    const int*   H     = (const int*)d_in[3];     // (144, 576)
    float* out = (float*)d_out;                   // (256, 576)

    // 144 warps for row extraction
    nms_prep_rows<<<18, 256>>>(H);
    // One CTA per frame
    nms_decode<<<B_FRAMES, BT>>>(r, alpha, beta, out);
}

// round 5
// speedup vs baseline: 1.0118x; 1.0118x over previous
#include <cuda_runtime.h>
#include <math.h>

// Problem constants (fixed by the reference)
#define B_FRAMES 256
#define N_COLS   576
#define MR_ROWS  144
#define Z_LIFT   24
#define N_IT     3
#define ROW_DEG  15
#define N_MSG    (MR_ROWS * ROW_DEG)   // 2160
#define NB_A     ((MR_ROWS / Z_LIFT) * (N_COLS / Z_LIFT) * N_IT)  // 432

#define FPB   2                        // frames per CTA
#define BT    512                      // threads per CTA (256 per frame)
#define GRID  (B_FRAMES / FPB)         // 128 CTAs -> 1 per SM, single wave

// Sparse row structure of H: 15 column indices per check row
__device__ int g_row_cols[N_MSG];

// ---------------------------------------------------------------------------
// Kernel 1: extract row structure via warp ballot compaction (one warp/row).
// ---------------------------------------------------------------------------
__global__ void nms_prep_rows(const int* __restrict__ H) {
    int warp = (blockIdx.x * blockDim.x + threadIdx.x) >> 5;
    int lane = threadIdx.x & 31;
    if (warp >= MR_ROWS) return;
    const int* row = H + warp * N_COLS;
    int cnt = 0;
    #pragma unroll
    for (int base = 0; base < N_COLS; base += 32) {
        int v = row[base + lane];
        unsigned ball = __ballot_sync(0xffffffffu, v != 0);
        int before = __popc(ball & ((1u << lane) - 1u));
        if (v != 0) g_row_cols[warp * ROW_DEG + cnt + before] = base + lane;
        cnt += __popc(ball);
    }
}

// ---------------------------------------------------------------------------
// Kernel 2: edge-parallel decoder. 2 frames/CTA, 16 lanes per check row.
// Per iteration: [zero write-buf] sync [edge pass: recompute v, butterfly
// min2+argmin, ballot sign product, E, atomic column sum] sync.
// ---------------------------------------------------------------------------
__global__ __launch_bounds__(BT) void nms_decode(
    const float* __restrict__ r,
    const float* __restrict__ alpha,
    const float* __restrict__ beta,
    float* __restrict__ out)
{
    __shared__ float s_r[FPB][N_COLS];
    __shared__ float s_sumE[FPB][2][N_COLS];   // double-buffered column sums
    __shared__ float s_E[FPB][N_MSG];          // single buffer: slot-owner RAW only
    __shared__ int   s_rc[N_MSG];
    __shared__ float s_a[NB_A];
    __shared__ float s_b[NB_A];

    const int tid = threadIdx.x;
    const int f   = tid >> 8;          // frame within CTA (0/1)
    const int ft  = tid & 255;         // thread id within frame
    const int grp = ft >> 4;           // 16-lane row group (0..15)
    const int k   = ft & 15;           // edge slot within row (15 = padding)
    const int b   = blockIdx.x * FPB + f;
    const bool act = (k < ROW_DEG);
    const unsigned hshift = (tid & 16);              // 0 or 16: which half-warp
    const unsigned hmask  = 0xFFFFu << hshift;

    // Stage inputs / init state
    for (int i = tid; i < N_MSG; i += BT) s_rc[i] = g_row_cols[i];
    for (int i = tid; i < NB_A;  i += BT) { s_a[i] = alpha[i]; s_b[i] = beta[i]; }
    for (int i = ft; i < N_COLS; i += 256) {
        s_r[f][i] = r[b * N_COLS + i];
        s_sumE[f][0][i] = 0.0f;
    }
    for (int i = ft; i < N_MSG; i += 256) s_E[f][i] = 0.0f;
    __syncthreads();

    for (int it = 0; it < N_IT; ++it) {
        const int pr = it & 1, cur = pr ^ 1;

        // Zero this iteration's column-sum buffer
        for (int i = ft; i < N_COLS; i += 256) s_sumE[f][cur][i] = 0.0f;
        __syncthreads();

        #pragma unroll
        for (int p = 0; p < MR_ROWS / 16; ++p) {        // 9 row passes
            const int row = p * 16 + grp;
            const int e   = row * ROW_DEG + k;

            int   c = 0;
            float v = 0.0f;
            if (act) {
                c = s_rc[e];
                v = s_r[f][c] + s_sumE[f][pr][c] - s_E[f][e];
            }
            float av = act ? fabsf(v) : INFINITY;

            // Row sign product: parity of negatives, zero-detect (per 16-lane group)
            unsigned negb = __ballot_sync(0xffffffffu, act && (v < 0.0f));
            unsigned zb   = __ballot_sync(0xffffffffu, act && (v == 0.0f));
            int  parity  = __popc(negb & hmask) & 1;
            bool anyzero = (zb & hmask) != 0u;

            // min1/min2/argmin butterfly over the 16-lane group
            float m1 = av, m2 = INFINITY;
            int   k1 = k;
            #pragma unroll
            for (int d = 1; d < 16; d <<= 1) {
                float om1 = __shfl_xor_sync(0xffffffffu, m1, d, 16);
                float om2 = __shfl_xor_sync(0xffffffffu, m2, d, 16);
                int   ok1 = __shfl_xor_sync(0xffffffffu, k1, d, 16);
                if (om1 < m1) { m2 = fminf(m1, om2); m1 = om1; k1 = ok1; }
                else          { m2 = fminf(m2, om1); }
            }

            if (act) {
                const float sel = (k == k1) ? m2 : m1;  // exclude self at argmin
                const int   bc  = c / Z_LIFT;
                const int   ai  = (row / Z_LIFT) * ((N_COLS / Z_LIFT) * N_IT)
                                + bc * N_IT + it;
                const float a   = s_a[ai];
                float mag = sel - s_b[ai];
                mag = (mag > 0.0f) ? mag : 0.0f;
                const int   neg = parity ^ ((v < 0.0f) ? 1 : 0);
                float E = a * mag;
                E = neg ? -E : E;
                E = anyzero ? 0.0f : E;
                s_E[f][e] = E;                          // only this thread reads slot e
                atomicAdd(&s_sumE[f][cur][c], E);
            }
        }
        __syncthreads();
    }

    // Posterior LLRs: last iteration (it=2) wrote buffer 1
    for (int i = ft; i < N_COLS; i += 256)
        out[b * N_COLS + i] = s_r[f][i] + s_sumE[f][1][i];
}

extern "C" void kernel_launch(void* const* d_in, const int* in_sizes, int n_in,
                              void* d_out, int out_size) {
    const float* r     = (const float*)d_in[0];   // (256, 576)
    const float* alpha = (const float*)d_in[1];   // (6, 24, 3)
    const float* beta  = (const float*)d_in[2];   // (6, 24, 3)
    const int*   H     = (const int*)d_in[3];     // (144, 576)
    float* out = (float*)d_out;                   // (256, 576)

    nms_prep_rows<<<18, 256>>>(H);
    nms_decode<<<GRID, BT>>>(r, alpha, beta, out);
}